// round 14
// baseline (speedup 1.0000x reference)
#include <cuda_runtime.h>
#include <math.h>
#include <stdint.h>

#define B_ 4
#define N_ 2048
#define C_ 512
#define H_ 8
#define HD_ 64
#define HIDE_ 2048
#define M_ (B_ * N_)   // 8192 rows

// Scratch (device globals: no cudaMalloc allowed)
__device__ float g_attn[(size_t)M_ * C_];
__device__ float g_q2[(size_t)M_ * C_];
__device__ float g_h[(size_t)M_ * HIDE_];

// ---------------------------------------------------------------------------
// MMA / cp.async helpers. Raw fp32 bits into mma.tf32 (HW truncates to tf32).
// ---------------------------------------------------------------------------
__device__ __forceinline__ void mma8(float* d,
                                     uint32_t a0, uint32_t a1, uint32_t a2, uint32_t a3,
                                     uint32_t b0, uint32_t b1) {
    asm volatile(
        "mma.sync.aligned.m16n8k8.row.col.f32.tf32.tf32.f32 "
        "{%0,%1,%2,%3}, {%4,%5,%6,%7}, {%8,%9}, {%0,%1,%2,%3};"
        : "+f"(d[0]), "+f"(d[1]), "+f"(d[2]), "+f"(d[3])
        : "r"(a0), "r"(a1), "r"(a2), "r"(a3), "r"(b0), "r"(b1));
}

__device__ __forceinline__ void cp16(uint32_t smem_addr, const void* gptr) {
    asm volatile("cp.async.cg.shared.global [%0], [%1], 16;" ::
                 "r"(smem_addr), "l"(gptr));
}
__device__ __forceinline__ void cp_commit() {
    asm volatile("cp.async.commit_group;");
}

// ---------------------------------------------------------------------------
// Flash attention (TF32 mma). 128 threads, 4 warps x 32 q-rows (2 m-tiles).
// KV tiles of 64, cp.async double-buffered. P goes acc->A-frag via shuffles
// (no smem round trip).  [frozen from R8 — proven]
// ---------------------------------------------------------------------------
#define AQS 68
#define AVS 72
#define KV_FLOATS (64 * AQS + 64 * AVS)
#define ATTN_SMEM ((128 * AQS + 2 * KV_FLOATS) * 4)

__global__ void __launch_bounds__(128)
attn_kernel(const float* __restrict__ q,
            const float* __restrict__ k,
            const float* __restrict__ v,
            float* __restrict__ out)
{
    extern __shared__ float sm[];
    float* Qs = sm;
    float* KV0 = sm + 128 * AQS;

    const int tid = threadIdx.x;
    const int lane = tid & 31;
    const int wid = tid >> 5;
    const int r0 = lane >> 2;
    const int c0 = lane & 3;

    const int src0 = (lane & ~3) | (c0 >> 1);
    const int src2 = src0 + 2;
    const bool podd = (c0 & 1);

    const int b = blockIdx.z;
    const int h = blockIdx.y;
    const int q0 = blockIdx.x * 128;

    const float* Qg = q + (size_t)(b * N_ + q0) * C_ + h * HD_;
    const float* Kg = k + (size_t)b * N_ * C_ + h * HD_;
    const float* Vg = v + (size_t)b * N_ * C_ + h * HD_;

    for (int i = tid; i < 128 * 16; i += 128) {
        int row = i >> 4;
        int col = (i & 15) * 4;
        float4 t = *(const float4*)(Qg + (size_t)row * C_ + col);
        Qs[row * AQS + col + 0] = t.x * 0.125f;
        Qs[row * AQS + col + 1] = t.y * 0.125f;
        Qs[row * AQS + col + 2] = t.z * 0.125f;
        Qs[row * AQS + col + 3] = t.w * 0.125f;
    }

    float o[2][8][4];
    float mrow[2][2], lrow[2][2];
#pragma unroll
    for (int mt = 0; mt < 2; mt++) {
#pragma unroll
        for (int h2 = 0; h2 < 2; h2++) { mrow[mt][h2] = -1e30f; lrow[mt][h2] = 0.0f; }
#pragma unroll
        for (int dt = 0; dt < 8; dt++)
#pragma unroll
            for (int rr = 0; rr < 4; rr++) o[mt][dt][rr] = 0.0f;
    }

    const int qbase = wid * 32;

    auto stage_kv = [&](int s, int kt) {
        const float* Kt = Kg + (size_t)kt * 64 * C_;
        const float* Vt = Vg + (size_t)kt * 64 * C_;
        float* Kd = KV0 + s * KV_FLOATS;
        float* Vd = Kd + 64 * AQS;
#pragma unroll
        for (int j = 0; j < 8; j++) {
            int i = j * 128 + tid;
            int row = i >> 4;
            int col = (i & 15) * 4;
            uint32_t dk = (uint32_t)__cvta_generic_to_shared(Kd + row * AQS + col);
            cp16(dk, Kt + (size_t)row * C_ + col);
            uint32_t dv = (uint32_t)__cvta_generic_to_shared(Vd + row * AVS + col);
            cp16(dv, Vt + (size_t)row * C_ + col);
        }
    };

    const int KT = N_ / 64;
    stage_kv(0, 0);
    cp_commit();

    for (int kt = 0; kt < KT; kt++) {
        asm volatile("cp.async.wait_group 0;");
        __syncthreads();
        if (kt + 1 < KT) {
            stage_kv((kt + 1) & 1, kt + 1);
            cp_commit();
        }

        const float* Ks = KV0 + (kt & 1) * KV_FLOATS;
        const float* Vs = Ks + 64 * AQS;

        float s[2][8][4];
#pragma unroll
        for (int mt = 0; mt < 2; mt++)
#pragma unroll
            for (int nt = 0; nt < 8; nt++)
#pragma unroll
                for (int rr = 0; rr < 4; rr++) s[mt][nt][rr] = 0.0f;

#pragma unroll
        for (int ks = 0; ks < 8; ks++) {
            int kc = ks * 8 + c0;
            uint32_t a[2][4];
#pragma unroll
            for (int mt = 0; mt < 2; mt++) {
                const float* Qr = Qs + (qbase + mt * 16 + r0) * AQS;
                a[mt][0] = __float_as_uint(Qr[kc]);
                a[mt][1] = __float_as_uint(Qr[8 * AQS + kc]);
                a[mt][2] = __float_as_uint(Qr[kc + 4]);
                a[mt][3] = __float_as_uint(Qr[8 * AQS + kc + 4]);
            }
#pragma unroll
            for (int nt = 0; nt < 8; nt++) {
                const float* Kr = Ks + (nt * 8 + r0) * AQS;
                uint32_t b0 = __float_as_uint(Kr[kc]);
                uint32_t b1 = __float_as_uint(Kr[kc + 4]);
                mma8(s[0][nt], a[0][0], a[0][1], a[0][2], a[0][3], b0, b1);
                mma8(s[1][nt], a[1][0], a[1][1], a[1][2], a[1][3], b0, b1);
            }
        }

#pragma unroll
        for (int mt = 0; mt < 2; mt++) {
#pragma unroll
            for (int h2 = 0; h2 < 2; h2++) {
                float mx = -1e30f;
#pragma unroll
                for (int nt = 0; nt < 8; nt++)
                    mx = fmaxf(mx, fmaxf(s[mt][nt][h2 * 2], s[mt][nt][h2 * 2 + 1]));
                mx = fmaxf(mx, __shfl_xor_sync(0xffffffffu, mx, 1));
                mx = fmaxf(mx, __shfl_xor_sync(0xffffffffu, mx, 2));
                float mnew = fmaxf(mrow[mt][h2], mx);
                float sum = 0.0f;
#pragma unroll
                for (int nt = 0; nt < 8; nt++) {
                    float p0 = __expf(s[mt][nt][h2 * 2] - mnew);
                    float p1 = __expf(s[mt][nt][h2 * 2 + 1] - mnew);
                    s[mt][nt][h2 * 2] = p0;
                    s[mt][nt][h2 * 2 + 1] = p1;
                    sum += p0 + p1;
                }
                sum += __shfl_xor_sync(0xffffffffu, sum, 1);
                sum += __shfl_xor_sync(0xffffffffu, sum, 2);
                float corr = __expf(mrow[mt][h2] - mnew);
                lrow[mt][h2] = lrow[mt][h2] * corr + sum;
                mrow[mt][h2] = mnew;
#pragma unroll
                for (int dt = 0; dt < 8; dt++) {
                    o[mt][dt][h2 * 2] *= corr;
                    o[mt][dt][h2 * 2 + 1] *= corr;
                }
            }
        }

#pragma unroll
        for (int g = 0; g < 8; g++) {
            uint32_t a[2][4];
#pragma unroll
            for (int mt = 0; mt < 2; mt++) {
                float e0 = __shfl_sync(0xffffffffu, s[mt][g][0], src0);
                float e1 = __shfl_sync(0xffffffffu, s[mt][g][1], src0);
                a[mt][0] = __float_as_uint(podd ? e1 : e0);
                float f0 = __shfl_sync(0xffffffffu, s[mt][g][2], src0);
                float f1 = __shfl_sync(0xffffffffu, s[mt][g][3], src0);
                a[mt][1] = __float_as_uint(podd ? f1 : f0);
                float g0 = __shfl_sync(0xffffffffu, s[mt][g][0], src2);
                float g1 = __shfl_sync(0xffffffffu, s[mt][g][1], src2);
                a[mt][2] = __float_as_uint(podd ? g1 : g0);
                float h0 = __shfl_sync(0xffffffffu, s[mt][g][2], src2);
                float h1 = __shfl_sync(0xffffffffu, s[mt][g][3], src2);
                a[mt][3] = __float_as_uint(podd ? h1 : h0);
            }
#pragma unroll
            for (int dt = 0; dt < 8; dt++) {
                uint32_t b0 = __float_as_uint(Vs[(g * 8 + c0) * AVS + dt * 8 + r0]);
                uint32_t b1 = __float_as_uint(Vs[(g * 8 + c0 + 4) * AVS + dt * 8 + r0]);
                mma8(o[0][dt], a[0][0], a[0][1], a[0][2], a[0][3], b0, b1);
                mma8(o[1][dt], a[1][0], a[1][1], a[1][2], a[1][3], b0, b1);
            }
        }
    }

#pragma unroll
    for (int mt = 0; mt < 2; mt++) {
        int row = q0 + qbase + mt * 16 + r0;
        float inv0 = 1.0f / lrow[mt][0];
        float inv1 = 1.0f / lrow[mt][1];
        float* O0 = out + (size_t)(b * N_ + row) * C_ + h * HD_;
        float* O1 = out + (size_t)(b * N_ + row + 8) * C_ + h * HD_;
#pragma unroll
        for (int dt = 0; dt < 8; dt++) {
            *(float2*)(O0 + dt * 8 + 2 * c0) =
                make_float2(o[mt][dt][0] * inv0, o[mt][dt][1] * inv0);
            *(float2*)(O1 + dt * 8 + 2 * c0) =
                make_float2(o[mt][dt][2] * inv1, o[mt][dt][3] * inv1);
        }
    }
}

// ---------------------------------------------------------------------------
// Fused (optional residual add) + LayerNorm. One block (128 thr) per row.
// ---------------------------------------------------------------------------
__global__ void ln_kernel(const float* __restrict__ x,
                          const float* __restrict__ res,
                          const float* __restrict__ w,
                          const float* __restrict__ bb,
                          float* __restrict__ out)
{
    const int row = blockIdx.x;
    const int tid = threadIdx.x;
    const int col = tid * 4;

    float4 a = *(const float4*)(x + (size_t)row * C_ + col);
    if (res != nullptr) {
        float4 r4 = *(const float4*)(res + (size_t)row * C_ + col);
        a.x += r4.x; a.y += r4.y; a.z += r4.z; a.w += r4.w;
    }
    float s = a.x + a.y + a.z + a.w;
    float ss = a.x * a.x + a.y * a.y + a.z * a.z + a.w * a.w;

#pragma unroll
    for (int off = 16; off >= 1; off >>= 1) {
        s += __shfl_xor_sync(0xffffffffu, s, off);
        ss += __shfl_xor_sync(0xffffffffu, ss, off);
    }
    __shared__ float red[8];
    int wid = tid >> 5;
    if ((tid & 31) == 0) { red[wid] = s; red[wid + 4] = ss; }
    __syncthreads();
    float tot = red[0] + red[1] + red[2] + red[3];
    float tot2 = red[4] + red[5] + red[6] + red[7];

    const float mean = tot * (1.0f / C_);
    const float var = tot2 * (1.0f / C_) - mean * mean;
    const float inv = rsqrtf(var + 1e-6f);

    float4 wv = *(const float4*)(w + col);
    float4 bv = *(const float4*)(bb + col);
    float4 o;
    o.x = (a.x - mean) * inv * wv.x + bv.x;
    o.y = (a.y - mean) * inv * wv.y + bv.y;
    o.z = (a.z - mean) * inv * wv.z + bv.z;
    o.w = (a.w - mean) * inv * wv.w + bv.w;
    *(float4*)(out + (size_t)row * C_ + col) = o;
}

// ---------------------------------------------------------------------------
// TF32 MMA GEMM: out[m][n] = epi( sum_k A[m][k]*W[n][k] + bias[n] )
// 128x128x32 tiles, 256 thr (8 warps 2x4, warp tile 64x32), cp.async 3-stage,
// ONE __syncthreads per k-step, wait_group 1 (stage kt+1 stays in flight).
// __launch_bounds__(256, 2): cap 128 regs -> 2 CTAs/SM.
// smem = 3 stages x 36.9KB = 110.6KB/CTA -> 221KB for 2 CTAs (fits 228KB).
// EPI==0: exact GELU.  EPI==1: + resid.
// ---------------------------------------------------------------------------
#define GSK 36
#define GEMM_STAGE_FLOATS (2 * 128 * GSK)       // As + Bs per stage
#define GEMM_SMEM (3 * GEMM_STAGE_FLOATS * 4)   // 3 stages

template <int EPI>
__global__ void __launch_bounds__(256, 2)
gemm_kernel(const float* __restrict__ A,
            const float* __restrict__ W,
            const float* __restrict__ bias,
            const float* __restrict__ resid,
            float* __restrict__ out,
            int Ndim, int Kdim)
{
    extern __shared__ float sm[];

    const int tid = threadIdx.x;
    const int lane = tid & 31;
    const int wid = tid >> 5;
    const int r0 = lane >> 2;
    const int c0 = lane & 3;
    const int wm = (wid >> 2) * 64;
    const int wn = (wid & 3) * 32;

    const int m0 = blockIdx.y * 128;
    const int n0 = blockIdx.x * 128;

    const float* Ab = A + (size_t)m0 * Kdim;
    const float* Wb = W + (size_t)n0 * Kdim;

    float acc[4][4][4];
#pragma unroll
    for (int mt = 0; mt < 4; mt++)
#pragma unroll
        for (int nt = 0; nt < 4; nt++)
#pragma unroll
            for (int rr = 0; rr < 4; rr++) acc[mt][nt][rr] = 0.0f;

    const int row_st = tid >> 3;            // 0..31
    const int col_st = (tid & 7) * 4;       // 0,4,..28

    auto stage = [&](int s, int k0) {
        float* As = sm + s * GEMM_STAGE_FLOATS;
        float* Bs = As + 128 * GSK;
#pragma unroll
        for (int c = 0; c < 4; c++) {
            int row = c * 32 + row_st;
            uint32_t da = (uint32_t)__cvta_generic_to_shared(As + row * GSK + col_st);
            cp16(da, Ab + (size_t)row * Kdim + k0 + col_st);
            uint32_t db = (uint32_t)__cvta_generic_to_shared(Bs + row * GSK + col_st);
            cp16(db, Wb + (size_t)row * Kdim + k0 + col_st);
        }
    };

    auto compute = [&](int s) {
        const float* As = sm + s * GEMM_STAGE_FLOATS;
        const float* Bs = As + 128 * GSK;
#pragma unroll
        for (int ks = 0; ks < 4; ks++) {
            int kc = ks * 8 + c0;
            uint32_t af[4][4], bf[4][2];
#pragma unroll
            for (int mt = 0; mt < 4; mt++) {
                const float* Ar = As + (wm + mt * 16 + r0) * GSK;
                af[mt][0] = __float_as_uint(Ar[kc]);
                af[mt][1] = __float_as_uint(Ar[8 * GSK + kc]);
                af[mt][2] = __float_as_uint(Ar[kc + 4]);
                af[mt][3] = __float_as_uint(Ar[8 * GSK + kc + 4]);
            }
#pragma unroll
            for (int nt = 0; nt < 4; nt++) {
                const float* Br = Bs + (wn + nt * 8 + r0) * GSK;
                bf[nt][0] = __float_as_uint(Br[kc]);
                bf[nt][1] = __float_as_uint(Br[kc + 4]);
            }
#pragma unroll
            for (int mt = 0; mt < 4; mt++)
#pragma unroll
                for (int nt = 0; nt < 4; nt++)
                    mma8(acc[mt][nt], af[mt][0], af[mt][1], af[mt][2], af[mt][3],
                         bf[nt][0], bf[nt][1]);
        }
    };

    const int KT = Kdim / 32;
    stage(0, 0);
    cp_commit();
    stage(1, 32);
    cp_commit();

    for (int kt = 0; kt < KT; kt++) {
        if (kt + 1 < KT) {
            asm volatile("cp.async.wait_group 1;");   // stage kt done; kt+1 in flight
        } else {
            asm volatile("cp.async.wait_group 0;");
        }
        __syncthreads();   // stage kt visible; compute kt-1 drained (WAR for kt+2)
        if (kt + 2 < KT) {
            stage((kt + 2) % 3, (kt + 2) * 32);       // overwrites buffer of kt-1
            cp_commit();
        }
        compute(kt % 3);
    }

    // Epilogue
#pragma unroll
    for (int mt = 0; mt < 4; mt++) {
        int row = m0 + wm + mt * 16 + r0;
#pragma unroll
        for (int half = 0; half < 2; half++) {
            int rrow = row + half * 8;
#pragma unroll
            for (int nt = 0; nt < 4; nt++) {
                int col = n0 + wn + nt * 8 + 2 * c0;
                float vx = acc[mt][nt][half * 2 + 0] + bias[col];
                float vy = acc[mt][nt][half * 2 + 1] + bias[col + 1];
                if (EPI == 0) {
                    vx = 0.5f * vx * (1.0f + erff(vx * 0.70710678118654752f));
                    vy = 0.5f * vy * (1.0f + erff(vy * 0.70710678118654752f));
                } else {
                    float2 r2 = *(const float2*)(resid + (size_t)rrow * Ndim + col);
                    vx += r2.x; vy += r2.y;
                }
                *(float2*)(out + (size_t)rrow * Ndim + col) = make_float2(vx, vy);
            }
        }
    }
}

// ---------------------------------------------------------------------------
extern "C" void kernel_launch(void* const* d_in, const int* in_sizes, int n_in,
                              void* d_out, int out_size)
{
    const float* q = (const float*)d_in[0];
    const float* k = (const float*)d_in[1];
    const float* v = (const float*)d_in[2];
    const float* fc1_w = (const float*)d_in[3];
    const float* fc1_b = (const float*)d_in[4];
    const float* fc2_w = (const float*)d_in[5];
    const float* fc2_b = (const float*)d_in[6];
    const float* ln1_w = (const float*)d_in[7];
    const float* ln1_b = (const float*)d_in[8];
    const float* ln2_w = (const float*)d_in[9];
    const float* ln2_b = (const float*)d_in[10];
    float* out = (float*)d_out;

    float *attn, *q2, *hbuf;
    cudaGetSymbolAddress((void**)&attn, g_attn);
    cudaGetSymbolAddress((void**)&q2, g_q2);
    cudaGetSymbolAddress((void**)&hbuf, g_h);

    cudaFuncSetAttribute(attn_kernel,
                         cudaFuncAttributeMaxDynamicSharedMemorySize, ATTN_SMEM);
    cudaFuncSetAttribute(gemm_kernel<0>,
                         cudaFuncAttributeMaxDynamicSharedMemorySize, GEMM_SMEM);
    cudaFuncSetAttribute(gemm_kernel<1>,
                         cudaFuncAttributeMaxDynamicSharedMemorySize, GEMM_SMEM);

    // 1) attention -> g_attn
    attn_kernel<<<dim3(N_ / 128, H_, B_), 128, ATTN_SMEM>>>(q, k, v, attn);

    // 2) q2 = LN1(q + attn)
    ln_kernel<<<M_, 128>>>(attn, q, ln1_w, ln1_b, q2);

    // 3) h = gelu(q2 @ fc1_w^T + fc1_b)
    gemm_kernel<0><<<dim3(HIDE_ / 128, M_ / 128), 256, GEMM_SMEM>>>(
        q2, fc1_w, fc1_b, nullptr, hbuf, HIDE_, C_);

    // 4) g_attn = q2 + (h @ fc2_w^T + fc2_b)
    gemm_kernel<1><<<dim3(C_ / 128, M_ / 128), 256, GEMM_SMEM>>>(
        hbuf, fc2_w, fc2_b, q2, attn, C_, HIDE_);

    // 5) out = LN2(g_attn)
    ln_kernel<<<M_, 128>>>(attn, nullptr, ln2_w, ln2_b, out);
}

// round 15
// speedup vs baseline: 1.0783x; 1.0783x over previous
#include <cuda_runtime.h>
#include <math.h>
#include <stdint.h>

#define B_ 4
#define N_ 2048
#define C_ 512
#define H_ 8
#define HD_ 64
#define HIDE_ 2048
#define M_ (B_ * N_)   // 8192 rows

// Scratch (device globals: no cudaMalloc allowed)
__device__ float g_attn[(size_t)M_ * C_];
__device__ float g_q2[(size_t)M_ * C_];
__device__ float g_h[(size_t)M_ * HIDE_];

// ---------------------------------------------------------------------------
// MMA / cp.async helpers. Raw fp32 bits into mma.tf32 (HW truncates to tf32).
// ---------------------------------------------------------------------------
__device__ __forceinline__ void mma8(float* d,
                                     uint32_t a0, uint32_t a1, uint32_t a2, uint32_t a3,
                                     uint32_t b0, uint32_t b1) {
    asm volatile(
        "mma.sync.aligned.m16n8k8.row.col.f32.tf32.tf32.f32 "
        "{%0,%1,%2,%3}, {%4,%5,%6,%7}, {%8,%9}, {%0,%1,%2,%3};"
        : "+f"(d[0]), "+f"(d[1]), "+f"(d[2]), "+f"(d[3])
        : "r"(a0), "r"(a1), "r"(a2), "r"(a3), "r"(b0), "r"(b1));
}

// bf16 m16n8k16 mma (2x MAC rate of tf32 k8)
__device__ __forceinline__ void mma16bf(float* d,
                                        uint32_t a0, uint32_t a1, uint32_t a2, uint32_t a3,
                                        uint32_t b0, uint32_t b1) {
    asm volatile(
        "mma.sync.aligned.m16n8k16.row.col.f32.bf16.bf16.f32 "
        "{%0,%1,%2,%3}, {%4,%5,%6,%7}, {%8,%9}, {%0,%1,%2,%3};"
        : "+f"(d[0]), "+f"(d[1]), "+f"(d[2]), "+f"(d[3])
        : "r"(a0), "r"(a1), "r"(a2), "r"(a3), "r"(b0), "r"(b1));
}

// pack two fp32 -> bf16x2 (lo = first arg, hi = second), round-to-nearest
__device__ __forceinline__ uint32_t packbf(float lo, float hi) {
    uint32_t r;
    asm("cvt.rn.bf16x2.f32 %0, %1, %2;" : "=r"(r) : "f"(hi), "f"(lo));
    return r;
}

__device__ __forceinline__ void cp16(uint32_t smem_addr, const void* gptr) {
    asm volatile("cp.async.cg.shared.global [%0], [%1], 16;" ::
                 "r"(smem_addr), "l"(gptr));
}
__device__ __forceinline__ void cp_commit() {
    asm volatile("cp.async.commit_group;");
}

// ---------------------------------------------------------------------------
// Flash attention. 128 threads, 4 warps x 32 q-rows (2 m-tiles).
// QK: tf32 m16n8k8 (score precision). PV: bf16 m16n8k16 — S-accumulator
// layout IS the bf16 A-frag layout (pairs 2c0,2c0+1), so P needs only cvt
// packs, no shuffles/smem. V packed from fp32 smem at load time.
// KV tiles of 64, cp.async double-buffered.
// smem: Qs[128][68] + 2 x { Ks[64][68], Vs[64][68] } = 102 KB -> 2 blk/SM.
// ---------------------------------------------------------------------------
#define AQS 68
#define AVS 68
#define KV_FLOATS (64 * AQS + 64 * AVS)
#define ATTN_SMEM ((128 * AQS + 2 * KV_FLOATS) * 4)

__global__ void __launch_bounds__(128)
attn_kernel(const float* __restrict__ q,
            const float* __restrict__ k,
            const float* __restrict__ v,
            float* __restrict__ out)
{
    extern __shared__ float sm[];
    float* Qs = sm;
    float* KV0 = sm + 128 * AQS;

    const int tid = threadIdx.x;
    const int lane = tid & 31;
    const int wid = tid >> 5;
    const int r0 = lane >> 2;
    const int c0 = lane & 3;

    const int b = blockIdx.z;
    const int h = blockIdx.y;
    const int q0 = blockIdx.x * 128;

    const float* Qg = q + (size_t)(b * N_ + q0) * C_ + h * HD_;
    const float* Kg = k + (size_t)b * N_ * C_ + h * HD_;
    const float* Vg = v + (size_t)b * N_ * C_ + h * HD_;

    for (int i = tid; i < 128 * 16; i += 128) {
        int row = i >> 4;
        int col = (i & 15) * 4;
        float4 t = *(const float4*)(Qg + (size_t)row * C_ + col);
        Qs[row * AQS + col + 0] = t.x * 0.125f;
        Qs[row * AQS + col + 1] = t.y * 0.125f;
        Qs[row * AQS + col + 2] = t.z * 0.125f;
        Qs[row * AQS + col + 3] = t.w * 0.125f;
    }

    float o[2][8][4];
    float mrow[2][2], lrow[2][2];
#pragma unroll
    for (int mt = 0; mt < 2; mt++) {
#pragma unroll
        for (int h2 = 0; h2 < 2; h2++) { mrow[mt][h2] = -1e30f; lrow[mt][h2] = 0.0f; }
#pragma unroll
        for (int dt = 0; dt < 8; dt++)
#pragma unroll
            for (int rr = 0; rr < 4; rr++) o[mt][dt][rr] = 0.0f;
    }

    const int qbase = wid * 32;

    auto stage_kv = [&](int s, int kt) {
        const float* Kt = Kg + (size_t)kt * 64 * C_;
        const float* Vt = Vg + (size_t)kt * 64 * C_;
        float* Kd = KV0 + s * KV_FLOATS;
        float* Vd = Kd + 64 * AQS;
#pragma unroll
        for (int j = 0; j < 8; j++) {
            int i = j * 128 + tid;
            int row = i >> 4;
            int col = (i & 15) * 4;
            uint32_t dk = (uint32_t)__cvta_generic_to_shared(Kd + row * AQS + col);
            cp16(dk, Kt + (size_t)row * C_ + col);
            uint32_t dv = (uint32_t)__cvta_generic_to_shared(Vd + row * AVS + col);
            cp16(dv, Vt + (size_t)row * C_ + col);
        }
    };

    const int KT = N_ / 64;
    stage_kv(0, 0);
    cp_commit();

    for (int kt = 0; kt < KT; kt++) {
        asm volatile("cp.async.wait_group 0;");
        __syncthreads();
        if (kt + 1 < KT) {
            stage_kv((kt + 1) & 1, kt + 1);
            cp_commit();
        }

        const float* Ks = KV0 + (kt & 1) * KV_FLOATS;
        const float* Vs = Ks + 64 * AQS;

        // S = Q @ K^T  (tf32)
        float s[2][8][4];
#pragma unroll
        for (int mt = 0; mt < 2; mt++)
#pragma unroll
            for (int nt = 0; nt < 8; nt++)
#pragma unroll
                for (int rr = 0; rr < 4; rr++) s[mt][nt][rr] = 0.0f;

#pragma unroll
        for (int ks = 0; ks < 8; ks++) {
            int kc = ks * 8 + c0;
            uint32_t a[2][4];
#pragma unroll
            for (int mt = 0; mt < 2; mt++) {
                const float* Qr = Qs + (qbase + mt * 16 + r0) * AQS;
                a[mt][0] = __float_as_uint(Qr[kc]);
                a[mt][1] = __float_as_uint(Qr[8 * AQS + kc]);
                a[mt][2] = __float_as_uint(Qr[kc + 4]);
                a[mt][3] = __float_as_uint(Qr[8 * AQS + kc + 4]);
            }
#pragma unroll
            for (int nt = 0; nt < 8; nt++) {
                const float* Kr = Ks + (nt * 8 + r0) * AQS;
                uint32_t b0 = __float_as_uint(Kr[kc]);
                uint32_t b1 = __float_as_uint(Kr[kc + 4]);
                mma8(s[0][nt], a[0][0], a[0][1], a[0][2], a[0][3], b0, b1);
                mma8(s[1][nt], a[1][0], a[1][1], a[1][2], a[1][3], b0, b1);
            }
        }

        // Online softmax
#pragma unroll
        for (int mt = 0; mt < 2; mt++) {
#pragma unroll
            for (int h2 = 0; h2 < 2; h2++) {
                float mx = -1e30f;
#pragma unroll
                for (int nt = 0; nt < 8; nt++)
                    mx = fmaxf(mx, fmaxf(s[mt][nt][h2 * 2], s[mt][nt][h2 * 2 + 1]));
                mx = fmaxf(mx, __shfl_xor_sync(0xffffffffu, mx, 1));
                mx = fmaxf(mx, __shfl_xor_sync(0xffffffffu, mx, 2));
                float mnew = fmaxf(mrow[mt][h2], mx);
                float sum = 0.0f;
#pragma unroll
                for (int nt = 0; nt < 8; nt++) {
                    float p0 = __expf(s[mt][nt][h2 * 2] - mnew);
                    float p1 = __expf(s[mt][nt][h2 * 2 + 1] - mnew);
                    s[mt][nt][h2 * 2] = p0;
                    s[mt][nt][h2 * 2 + 1] = p1;
                    sum += p0 + p1;
                }
                sum += __shfl_xor_sync(0xffffffffu, sum, 1);
                sum += __shfl_xor_sync(0xffffffffu, sum, 2);
                float corr = __expf(mrow[mt][h2] - mnew);
                lrow[mt][h2] = lrow[mt][h2] * corr + sum;
                mrow[mt][h2] = mnew;
#pragma unroll
                for (int dt = 0; dt < 8; dt++) {
                    o[mt][dt][h2 * 2] *= corr;
                    o[mt][dt][h2 * 2 + 1] *= corr;
                }
            }
        }

        // O += P @ V  (bf16 k16). S-acc cols {2c0,2c0+1} == bf16 A-frag pairs:
        // a0={r0, k=2c0,2c0+1 of slab 2j}, a1={r0+8,...}, a2/a3 = slab 2j+1.
        // B: V rows 16j+2c0, +1 (b0) and +8, +9 (b1) at dim dt*8+r0.
#pragma unroll
        for (int j = 0; j < 4; j++) {
            uint32_t a[2][4];
#pragma unroll
            for (int mt = 0; mt < 2; mt++) {
                a[mt][0] = packbf(s[mt][2 * j][0],     s[mt][2 * j][1]);
                a[mt][1] = packbf(s[mt][2 * j][2],     s[mt][2 * j][3]);
                a[mt][2] = packbf(s[mt][2 * j + 1][0], s[mt][2 * j + 1][1]);
                a[mt][3] = packbf(s[mt][2 * j + 1][2], s[mt][2 * j + 1][3]);
            }
#pragma unroll
            for (int dt = 0; dt < 8; dt++) {
                const float* Vr = Vs + (j * 16 + 2 * c0) * AVS + dt * 8 + r0;
                uint32_t b0 = packbf(Vr[0], Vr[AVS]);
                uint32_t b1 = packbf(Vr[8 * AVS], Vr[9 * AVS]);
                mma16bf(o[0][dt], a[0][0], a[0][1], a[0][2], a[0][3], b0, b1);
                mma16bf(o[1][dt], a[1][0], a[1][1], a[1][2], a[1][3], b0, b1);
            }
        }
    }

    // Epilogue
#pragma unroll
    for (int mt = 0; mt < 2; mt++) {
        int row = q0 + qbase + mt * 16 + r0;
        float inv0 = 1.0f / lrow[mt][0];
        float inv1 = 1.0f / lrow[mt][1];
        float* O0 = out + (size_t)(b * N_ + row) * C_ + h * HD_;
        float* O1 = out + (size_t)(b * N_ + row + 8) * C_ + h * HD_;
#pragma unroll
        for (int dt = 0; dt < 8; dt++) {
            *(float2*)(O0 + dt * 8 + 2 * c0) =
                make_float2(o[mt][dt][0] * inv0, o[mt][dt][1] * inv0);
            *(float2*)(O1 + dt * 8 + 2 * c0) =
                make_float2(o[mt][dt][2] * inv1, o[mt][dt][3] * inv1);
        }
    }
}

// ---------------------------------------------------------------------------
// Fused (optional residual add) + LayerNorm. One block (128 thr) per row.
// ---------------------------------------------------------------------------
__global__ void ln_kernel(const float* __restrict__ x,
                          const float* __restrict__ res,
                          const float* __restrict__ w,
                          const float* __restrict__ bb,
                          float* __restrict__ out)
{
    const int row = blockIdx.x;
    const int tid = threadIdx.x;
    const int col = tid * 4;

    float4 a = *(const float4*)(x + (size_t)row * C_ + col);
    if (res != nullptr) {
        float4 r4 = *(const float4*)(res + (size_t)row * C_ + col);
        a.x += r4.x; a.y += r4.y; a.z += r4.z; a.w += r4.w;
    }
    float s = a.x + a.y + a.z + a.w;
    float ss = a.x * a.x + a.y * a.y + a.z * a.z + a.w * a.w;

#pragma unroll
    for (int off = 16; off >= 1; off >>= 1) {
        s += __shfl_xor_sync(0xffffffffu, s, off);
        ss += __shfl_xor_sync(0xffffffffu, ss, off);
    }
    __shared__ float red[8];
    int wid = tid >> 5;
    if ((tid & 31) == 0) { red[wid] = s; red[wid + 4] = ss; }
    __syncthreads();
    float tot = red[0] + red[1] + red[2] + red[3];
    float tot2 = red[4] + red[5] + red[6] + red[7];

    const float mean = tot * (1.0f / C_);
    const float var = tot2 * (1.0f / C_) - mean * mean;
    const float inv = rsqrtf(var + 1e-6f);

    float4 wv = *(const float4*)(w + col);
    float4 bv = *(const float4*)(bb + col);
    float4 o;
    o.x = (a.x - mean) * inv * wv.x + bv.x;
    o.y = (a.y - mean) * inv * wv.y + bv.y;
    o.z = (a.z - mean) * inv * wv.z + bv.z;
    o.w = (a.w - mean) * inv * wv.w + bv.w;
    *(float4*)(out + (size_t)row * C_ + col) = o;
}

// ---------------------------------------------------------------------------
// TF32 MMA GEMM [R10 config — proven best: 2-stage, single barrier, reg cap]
// 128x128x32 tiles, 256 thr (8 warps 2x4, warp tile 64x32).
// EPI==0: exact GELU.  EPI==1: + resid.
// ---------------------------------------------------------------------------
#define GSK 36
#define GEMM_STAGE_FLOATS (2 * 128 * GSK)       // As + Bs per stage
#define GEMM_SMEM (2 * GEMM_STAGE_FLOATS * 4)   // 2 stages

template <int EPI>
__global__ void __launch_bounds__(256, 2)
gemm_kernel(const float* __restrict__ A,
            const float* __restrict__ W,
            const float* __restrict__ bias,
            const float* __restrict__ resid,
            float* __restrict__ out,
            int Ndim, int Kdim)
{
    extern __shared__ float sm[];

    const int tid = threadIdx.x;
    const int lane = tid & 31;
    const int wid = tid >> 5;
    const int r0 = lane >> 2;
    const int c0 = lane & 3;
    const int wm = (wid >> 2) * 64;
    const int wn = (wid & 3) * 32;

    const int m0 = blockIdx.y * 128;
    const int n0 = blockIdx.x * 128;

    const float* Ab = A + (size_t)m0 * Kdim;
    const float* Wb = W + (size_t)n0 * Kdim;

    float acc[4][4][4];
#pragma unroll
    for (int mt = 0; mt < 4; mt++)
#pragma unroll
        for (int nt = 0; nt < 4; nt++)
#pragma unroll
            for (int rr = 0; rr < 4; rr++) acc[mt][nt][rr] = 0.0f;

    const int row_st = tid >> 3;            // 0..31
    const int col_st = (tid & 7) * 4;       // 0,4,..28

    auto stage = [&](int s, int k0) {
        float* As = sm + s * GEMM_STAGE_FLOATS;
        float* Bs = As + 128 * GSK;
#pragma unroll
        for (int c = 0; c < 4; c++) {
            int row = c * 32 + row_st;
            uint32_t da = (uint32_t)__cvta_generic_to_shared(As + row * GSK + col_st);
            cp16(da, Ab + (size_t)row * Kdim + k0 + col_st);
            uint32_t db = (uint32_t)__cvta_generic_to_shared(Bs + row * GSK + col_st);
            cp16(db, Wb + (size_t)row * Kdim + k0 + col_st);
        }
    };

    auto compute = [&](int s) {
        const float* As = sm + s * GEMM_STAGE_FLOATS;
        const float* Bs = As + 128 * GSK;
#pragma unroll
        for (int ks = 0; ks < 4; ks++) {
            int kc = ks * 8 + c0;
            uint32_t af[4][4], bf[4][2];
#pragma unroll
            for (int mt = 0; mt < 4; mt++) {
                const float* Ar = As + (wm + mt * 16 + r0) * GSK;
                af[mt][0] = __float_as_uint(Ar[kc]);
                af[mt][1] = __float_as_uint(Ar[8 * GSK + kc]);
                af[mt][2] = __float_as_uint(Ar[kc + 4]);
                af[mt][3] = __float_as_uint(Ar[8 * GSK + kc + 4]);
            }
#pragma unroll
            for (int nt = 0; nt < 4; nt++) {
                const float* Br = Bs + (wn + nt * 8 + r0) * GSK;
                bf[nt][0] = __float_as_uint(Br[kc]);
                bf[nt][1] = __float_as_uint(Br[kc + 4]);
            }
#pragma unroll
            for (int mt = 0; mt < 4; mt++)
#pragma unroll
                for (int nt = 0; nt < 4; nt++)
                    mma8(acc[mt][nt], af[mt][0], af[mt][1], af[mt][2], af[mt][3],
                         bf[nt][0], bf[nt][1]);
        }
    };

    const int KT = Kdim / 32;
    stage(0, 0);
    cp_commit();

    for (int kt = 0; kt < KT; kt++) {
        asm volatile("cp.async.wait_group 0;");   // stage kt arrived
        __syncthreads();                           // visible to all; compute kt-1 done
        if (kt + 1 < KT) {
            stage((kt + 1) & 1, (kt + 1) * 32);    // overwrites buffer of kt-1 (safe)
            cp_commit();
        }
        compute(kt & 1);
    }

    // Epilogue
#pragma unroll
    for (int mt = 0; mt < 4; mt++) {
        int row = m0 + wm + mt * 16 + r0;
#pragma unroll
        for (int half = 0; half < 2; half++) {
            int rrow = row + half * 8;
#pragma unroll
            for (int nt = 0; nt < 4; nt++) {
                int col = n0 + wn + nt * 8 + 2 * c0;
                float vx = acc[mt][nt][half * 2 + 0] + bias[col];
                float vy = acc[mt][nt][half * 2 + 1] + bias[col + 1];
                if (EPI == 0) {
                    vx = 0.5f * vx * (1.0f + erff(vx * 0.70710678118654752f));
                    vy = 0.5f * vy * (1.0f + erff(vy * 0.70710678118654752f));
                } else {
                    float2 r2 = *(const float2*)(resid + (size_t)rrow * Ndim + col);
                    vx += r2.x; vy += r2.y;
                }
                *(float2*)(out + (size_t)rrow * Ndim + col) = make_float2(vx, vy);
            }
        }
    }
}

// ---------------------------------------------------------------------------
extern "C" void kernel_launch(void* const* d_in, const int* in_sizes, int n_in,
                              void* d_out, int out_size)
{
    const float* q = (const float*)d_in[0];
    const float* k = (const float*)d_in[1];
    const float* v = (const float*)d_in[2];
    const float* fc1_w = (const float*)d_in[3];
    const float* fc1_b = (const float*)d_in[4];
    const float* fc2_w = (const float*)d_in[5];
    const float* fc2_b = (const float*)d_in[6];
    const float* ln1_w = (const float*)d_in[7];
    const float* ln1_b = (const float*)d_in[8];
    const float* ln2_w = (const float*)d_in[9];
    const float* ln2_b = (const float*)d_in[10];
    float* out = (float*)d_out;

    float *attn, *q2, *hbuf;
    cudaGetSymbolAddress((void**)&attn, g_attn);
    cudaGetSymbolAddress((void**)&q2, g_q2);
    cudaGetSymbolAddress((void**)&hbuf, g_h);

    cudaFuncSetAttribute(attn_kernel,
                         cudaFuncAttributeMaxDynamicSharedMemorySize, ATTN_SMEM);
    cudaFuncSetAttribute(gemm_kernel<0>,
                         cudaFuncAttributeMaxDynamicSharedMemorySize, GEMM_SMEM);
    cudaFuncSetAttribute(gemm_kernel<1>,
                         cudaFuncAttributeMaxDynamicSharedMemorySize, GEMM_SMEM);

    // 1) attention -> g_attn
    attn_kernel<<<dim3(N_ / 128, H_, B_), 128, ATTN_SMEM>>>(q, k, v, attn);

    // 2) q2 = LN1(q + attn)
    ln_kernel<<<M_, 128>>>(attn, q, ln1_w, ln1_b, q2);

    // 3) h = gelu(q2 @ fc1_w^T + fc1_b)
    gemm_kernel<0><<<dim3(HIDE_ / 128, M_ / 128), 256, GEMM_SMEM>>>(
        q2, fc1_w, fc1_b, nullptr, hbuf, HIDE_, C_);

    // 4) g_attn = q2 + (h @ fc2_w^T + fc2_b)
    gemm_kernel<1><<<dim3(C_ / 128, M_ / 128), 256, GEMM_SMEM>>>(
        hbuf, fc2_w, fc2_b, q2, attn, C_, HIDE_);

    // 5) out = LN2(g_attn)
    ln_kernel<<<M_, 128>>>(attn, nullptr, ln2_w, ln2_b, out);
}